// round 3
// baseline (speedup 1.0000x reference)
#include <cuda_runtime.h>
#include <cuda_bf16.h>
#include <math.h>
#include <float.h>
#include <stdint.h>

// Problem constants
#define BATCH 16
#define PAIRS 8
#define NPTS  2048
#define DIM   256

// GEMM tiling
#define BM 128
#define BN 128
#define BKH 32          // bf16 elements per k-block
#define SW 20           // smem row stride in uint32 (16 data + 4 pad) -> conflict-free

// stats chunking
#define RCH 16
#define NCHUNK (NPTS / RCH)   // 128

// ---------------- device scratch ----------------
__device__ __nv_bfloat16 g_mdescH[(size_t)BATCH * NPTS * DIM];    // 16.8 MB
__device__ float  g_S[(size_t)PAIRS * NPTS * NPTS];               // 134 MB
__device__ float  g_lsP[BATCH * NPTS];
__device__ float  g_lsN[BATCH * NPTS];
__device__ float2 g_rstat[PAIRS * NPTS];
__device__ float2 g_cpart[(size_t)NCHUNK * PAIRS * NPTS];         // 16.8 MB
__device__ float2 g_cstat[PAIRS * NPTS];

// ---------------- helpers ----------------
__device__ __forceinline__ unsigned pack_bf16(float lo, float hi) {
    unsigned r;
    asm("cvt.rn.bf16x2.f32 %0, %1, %2;" : "=r"(r) : "f"(hi), "f"(lo));
    return r;
}

__device__ __forceinline__ void mma_bf16(float c[4], const unsigned a[4], const unsigned b[2]) {
    asm volatile(
        "mma.sync.aligned.m16n8k16.row.col.f32.bf16.bf16.f32 "
        "{%0,%1,%2,%3},{%4,%5,%6,%7},{%8,%9},{%0,%1,%2,%3};"
        : "+f"(c[0]), "+f"(c[1]), "+f"(c[2]), "+f"(c[3])
        : "r"(a[0]), "r"(a[1]), "r"(a[2]), "r"(a[3]), "r"(b[0]), "r"(b[1]));
}

__device__ __forceinline__ void ldsm_x4(unsigned r[4], uint32_t addr) {
    asm volatile("ldmatrix.sync.aligned.m8n8.x4.shared.b16 {%0,%1,%2,%3}, [%4];"
        : "=r"(r[0]), "=r"(r[1]), "=r"(r[2]), "=r"(r[3]) : "r"(addr));
}
__device__ __forceinline__ void ldsm_x2(unsigned r[2], uint32_t addr) {
    asm volatile("ldmatrix.sync.aligned.m8n8.x2.shared.b16 {%0,%1}, [%2];"
        : "=r"(r[0]), "=r"(r[1]) : "r"(addr));
}

__device__ __forceinline__ float logsigmoidf(float x) {
    return fminf(x, 0.f) - log1pf(expf(-fabsf(x)));
}

__device__ __forceinline__ float warpSum(float v) {
    #pragma unroll
    for (int o = 16; o > 0; o >>= 1) v += __shfl_xor_sync(0xffffffffu, v, o);
    return v;
}

__device__ __forceinline__ void lse_combine(float& M, float& S, float m2, float s2) {
    float Mn = fmaxf(M, m2);
    S = S * __expf(M - Mn) + s2 * __expf(m2 - Mn);
    M = Mn;
}

// ---------------- K1: projection GEMM (fp32 in -> bf16 mma -> bf16 out) ----------------
__global__ __launch_bounds__(256) void proj_gemm(const float* __restrict__ A,
                                                 const float* __restrict__ W,
                                                 const float* __restrict__ bias) {
    __shared__ unsigned sA[BM][SW];
    __shared__ unsigned sB[BN][SW];

    const int tid = threadIdx.x;
    const int wid = tid >> 5, lane = tid & 31;
    const int wm = wid >> 2, wn = wid & 3;     // 2x4 warp grid, warp tile 64x32
    const int g = lane >> 2, t = lane & 3;

    const int a_row = (lane & 7) + ((lane >> 3) & 1) * 8;
    const int a_col = (lane >> 4) * 4;
    const int b_row = (lane & 7);
    const int b_col = ((lane >> 3) & 1) * 4;

    const int rowBase = blockIdx.y * BM;
    const int colBase = blockIdx.x * BN;

    const uint32_t sA0 = (uint32_t)__cvta_generic_to_shared(&sA[0][0]);
    const uint32_t sB0 = (uint32_t)__cvta_generic_to_shared(&sB[0][0]);

    float acc[4][4][4];
    #pragma unroll
    for (int mi = 0; mi < 4; mi++)
        #pragma unroll
        for (int ni = 0; ni < 4; ni++)
            #pragma unroll
            for (int e = 0; e < 4; e++) acc[mi][ni][e] = 0.f;

    for (int kb = 0; kb < DIM; kb += BKH) {
        #pragma unroll
        for (int i = 0; i < 4; i++) {
            int idx = tid + i * 256;
            int r = idx >> 3;
            int c4 = idx & 7;
            float4 va = *(const float4*)(A + (size_t)(rowBase + r) * DIM + kb + c4 * 4);
            sA[r][c4 * 2 + 0] = pack_bf16(va.x, va.y);
            sA[r][c4 * 2 + 1] = pack_bf16(va.z, va.w);
            float4 vb = *(const float4*)(W + (size_t)(colBase + r) * DIM + kb + c4 * 4);
            sB[r][c4 * 2 + 0] = pack_bf16(vb.x, vb.y);
            sB[r][c4 * 2 + 1] = pack_bf16(vb.z, vb.w);
        }
        __syncthreads();

        #pragma unroll
        for (int ks = 0; ks < 2; ks++) {
            const int j0 = ks * 8;
            unsigned a[4][4], b[4][2];
            #pragma unroll
            for (int mi = 0; mi < 4; mi++)
                ldsm_x4(a[mi], sA0 + ((wm * 64 + mi * 16 + a_row) * SW + j0 + a_col) * 4u);
            #pragma unroll
            for (int ni = 0; ni < 4; ni++)
                ldsm_x2(b[ni], sB0 + ((wn * 32 + ni * 8 + b_row) * SW + j0 + b_col) * 4u);
            #pragma unroll
            for (int mi = 0; mi < 4; mi++)
                #pragma unroll
                for (int ni = 0; ni < 4; ni++)
                    mma_bf16(acc[mi][ni], a[mi], b[ni]);
        }
        __syncthreads();
    }

    #pragma unroll
    for (int mi = 0; mi < 4; mi++) {
        #pragma unroll
        for (int ni = 0; ni < 4; ni++) {
            #pragma unroll
            for (int eh = 0; eh < 2; eh++) {
                int row = rowBase + wm * 64 + mi * 16 + g + eh * 8;
                int col = colBase + wn * 32 + ni * 8 + 2 * t;
                float v0 = (acc[mi][ni][eh * 2 + 0] + bias[col])     * 0.25f;
                float v1 = (acc[mi][ni][eh * 2 + 1] + bias[col + 1]) * 0.25f;
                *(unsigned*)&g_mdescH[(size_t)row * DIM + col] = pack_bf16(v0, v1);
            }
        }
    }
}

// ---------------- K2: similarity GEMM (bf16, ldmatrix, double-buffered) ----------------
__global__ __launch_bounds__(256) void sim_gemm(const int* __restrict__ mask) {
    __shared__ unsigned sA[2][BM][SW];
    __shared__ unsigned sB[2][BN][SW];

    const int tid = threadIdx.x;
    const int wid = tid >> 5, lane = tid & 31;
    const int wm = wid >> 2, wn = wid & 3;
    const int g = lane >> 2, t = lane & 3;

    const int a_row = (lane & 7) + ((lane >> 3) & 1) * 8;
    const int a_col = (lane >> 4) * 4;
    const int b_row = (lane & 7);
    const int b_col = ((lane >> 3) & 1) * 4;

    const int p = blockIdx.z;
    const int rowBase = blockIdx.y * BM;
    const int colBase = blockIdx.x * BN;

    const __nv_bfloat16* Ap = g_mdescH + (size_t)(2 * p) * NPTS * DIM;
    const __nv_bfloat16* Bp = g_mdescH + (size_t)(2 * p + 1) * NPTS * DIM;

    const uint32_t sAb[2] = { (uint32_t)__cvta_generic_to_shared(&sA[0][0][0]),
                              (uint32_t)__cvta_generic_to_shared(&sA[1][0][0]) };
    const uint32_t sBb[2] = { (uint32_t)__cvta_generic_to_shared(&sB[0][0][0]),
                              (uint32_t)__cvta_generic_to_shared(&sB[1][0][0]) };

    float acc[4][4][4];
    #pragma unroll
    for (int mi = 0; mi < 4; mi++)
        #pragma unroll
        for (int ni = 0; ni < 4; ni++)
            #pragma unroll
            for (int e = 0; e < 4; e++) acc[mi][ni][e] = 0.f;

    const int r_ld[2]  = { tid >> 2, (tid + 256) >> 2 };
    const int c4_ld[2] = { tid & 3,  (tid + 256) & 3 };

    uint4 pa[2], pb[2];
    #pragma unroll
    for (int i = 0; i < 2; i++) {
        pa[i] = *(const uint4*)(Ap + (size_t)(rowBase + r_ld[i]) * DIM + c4_ld[i] * 8);
        pb[i] = *(const uint4*)(Bp + (size_t)(colBase + r_ld[i]) * DIM + c4_ld[i] * 8);
    }
    #pragma unroll
    for (int i = 0; i < 2; i++) {
        *(uint4*)&sA[0][r_ld[i]][c4_ld[i] * 4] = pa[i];
        *(uint4*)&sB[0][r_ld[i]][c4_ld[i] * 4] = pb[i];
    }
    __syncthreads();

    const int NKB = DIM / BKH;  // 8
    for (int kb = 0; kb < NKB; kb++) {
        const int cur = kb & 1;
        if (kb + 1 < NKB) {
            #pragma unroll
            for (int i = 0; i < 2; i++) {
                pa[i] = *(const uint4*)(Ap + (size_t)(rowBase + r_ld[i]) * DIM + (kb + 1) * BKH + c4_ld[i] * 8);
                pb[i] = *(const uint4*)(Bp + (size_t)(colBase + r_ld[i]) * DIM + (kb + 1) * BKH + c4_ld[i] * 8);
            }
        }

        #pragma unroll
        for (int ks = 0; ks < 2; ks++) {
            const int j0 = ks * 8;
            unsigned a[4][4], b[4][2];
            #pragma unroll
            for (int mi = 0; mi < 4; mi++)
                ldsm_x4(a[mi], sAb[cur] + ((wm * 64 + mi * 16 + a_row) * SW + j0 + a_col) * 4u);
            #pragma unroll
            for (int ni = 0; ni < 4; ni++)
                ldsm_x2(b[ni], sBb[cur] + ((wn * 32 + ni * 8 + b_row) * SW + j0 + b_col) * 4u);
            #pragma unroll
            for (int mi = 0; mi < 4; mi++)
                #pragma unroll
                for (int ni = 0; ni < 4; ni++)
                    mma_bf16(acc[mi][ni], a[mi], b[ni]);
        }

        if (kb + 1 < NKB) {
            const int nxt = (kb + 1) & 1;
            #pragma unroll
            for (int i = 0; i < 2; i++) {
                *(uint4*)&sA[nxt][r_ld[i]][c4_ld[i] * 4] = pa[i];
                *(uint4*)&sB[nxt][r_ld[i]][c4_ld[i] * 4] = pb[i];
            }
            __syncthreads();
        }
    }

    // mask epilogue; masked entries are EXACTLY -FLT_MAX
    const int* m0 = mask + (size_t)(2 * p) * NPTS;
    const int* m1 = mask + (size_t)(2 * p + 1) * NPTS;
    float* Sp = g_S + (size_t)p * NPTS * NPTS;

    #pragma unroll
    for (int mi = 0; mi < 4; mi++) {
        int rm[2];
        rm[0] = m0[rowBase + wm * 64 + mi * 16 + g];
        rm[1] = m0[rowBase + wm * 64 + mi * 16 + g + 8];
        #pragma unroll
        for (int ni = 0; ni < 4; ni++) {
            int col = colBase + wn * 32 + ni * 8 + 2 * t;
            int cm0 = m1[col], cm1 = m1[col + 1];
            #pragma unroll
            for (int eh = 0; eh < 2; eh++) {
                int row = rowBase + wm * 64 + mi * 16 + g + eh * 8;
                float2 v;
                v.x = (rm[eh] && cm0) ? acc[mi][ni][eh * 2 + 0] : -FLT_MAX;
                v.y = (rm[eh] && cm1) ? acc[mi][ni][eh * 2 + 1] : -FLT_MAX;
                *(float2*)&Sp[(size_t)row * NPTS + col] = v;
            }
        }
    }
}

// ---------------- K_match ----------------
__global__ __launch_bounds__(256) void match_kernel(const float* __restrict__ desc,
                                                    const float* __restrict__ mw,
                                                    const float* __restrict__ mb) {
    int warp = blockIdx.x * 8 + (threadIdx.x >> 5);
    int lane = threadIdx.x & 31;
    const float* dp = desc + (size_t)warp * DIM;
    float acc = 0.f;
    #pragma unroll
    for (int i = 0; i < 8; i++)
        acc = fmaf(dp[lane + 32 * i], mw[lane + 32 * i], acc);
    acc = warpSum(acc);
    if (lane == 0) {
        float m = acc + mb[0];
        g_lsP[warp] = logsigmoidf(m);
        g_lsN[warp] = logsigmoidf(-m);
    }
}

// ---------------- K3: fused row+col stats (16-row chunks, deferred row reduce) ----------------
__global__ __launch_bounds__(256) void stats_kernel() {
    const int p = blockIdx.y;
    const int r0 = blockIdx.x * RCH;
    const int tid = threadIdx.x;
    const int wrp = tid >> 5, lane = tid & 31;

    __shared__ float2 rp[RCH][256];   // 32 KB: per-row per-thread (max, sumexp) partials

    float colM[8], colS[8];
    #pragma unroll
    for (int i = 0; i < 8; i++) { colM[i] = -FLT_MAX; colS[i] = 0.f; }

    #pragma unroll 2
    for (int r = 0; r < RCH; r++) {
        const float* row = g_S + ((size_t)p * NPTS + r0 + r) * NPTS;
        float v[8];
        #pragma unroll
        for (int i = 0; i < 8; i++) v[i] = row[tid + 256 * i];

        float m = v[0];
        #pragma unroll
        for (int i = 1; i < 8; i++) m = fmaxf(m, v[i]);
        float s = 0.f;
        #pragma unroll
        for (int i = 0; i < 8; i++) s += __expf(v[i] - m);
        rp[r][tid] = make_float2(m, s);

        #pragma unroll
        for (int i = 0; i < 8; i++) {
            float x = v[i];
            if (x > colM[i]) { colS[i] = colS[i] * __expf(colM[i] - x) + 1.f; colM[i] = x; }
            else             { colS[i] += __expf(x - colM[i]); }
        }
    }
    __syncthreads();

    // row reductions: warp w handles rows 2w, 2w+1
    #pragma unroll
    for (int rr = 0; rr < 2; rr++) {
        int r = wrp * 2 + rr;
        float2 x = rp[r][lane];
        float M = x.x, S = x.y;
        #pragma unroll
        for (int j = 1; j < 8; j++) {
            float2 y = rp[r][lane + 32 * j];
            lse_combine(M, S, y.x, y.y);
        }
        #pragma unroll
        for (int o = 16; o > 0; o >>= 1) {
            float om = __shfl_xor_sync(0xffffffffu, M, o);
            float os = __shfl_xor_sync(0xffffffffu, S, o);
            lse_combine(M, S, om, os);
        }
        if (lane == 0) g_rstat[p * NPTS + r0 + r] = make_float2(M, __logf(S));
    }

    // col partials for this chunk
    #pragma unroll
    for (int i = 0; i < 8; i++) {
        int c = tid + 256 * i;
        g_cpart[((size_t)blockIdx.x * PAIRS + p) * NPTS + c] = make_float2(colM[i], colS[i]);
    }
}

__global__ __launch_bounds__(256) void col_lse_merge() {
    int idx = blockIdx.x * 256 + threadIdx.x;       // p*NPTS + c
    if (idx >= PAIRS * NPTS) return;
    float2 a = g_cpart[idx];
    float M = a.x, S = a.y;
    for (int ch = 1; ch < NCHUNK; ch++) {
        float2 b = g_cpart[(size_t)ch * PAIRS * NPTS + idx];
        lse_combine(M, S, b.x, b.y);
    }
    g_cstat[idx] = make_float2(M, __logf(S));
}

// ---------------- K5: final assembly ----------------
#define NOUT (NPTS + 1)
__global__ __launch_bounds__(256) void final_kernel(float* __restrict__ out) {
    const int m = blockIdx.x * 256 + threadIdx.x;
    const int n = blockIdx.y;
    const int p = blockIdx.z;
    if (m > NPTS) return;

    float* o = out + (((size_t)p * NOUT) + n) * NOUT + m;
    if (n < NPTS && m < NPTS) {
        float s = g_S[((size_t)p * NPTS + n) * NPTS + m];
        float2 r = g_rstat[p * NPTS + n];
        float2 c = g_cstat[p * NPTS + m];
        float sc0 = (s - r.x) - r.y;
        float sc1 = (s - c.x) - c.y;
        float cert = g_lsP[(2 * p) * NPTS + n] + g_lsP[(2 * p + 1) * NPTS + m];
        *o = (sc0 + sc1) + cert;
    } else if (n == NPTS && m < NPTS) {
        *o = g_lsN[(2 * p + 1) * NPTS + m];
    } else if (m == NPTS && n < NPTS) {
        *o = g_lsN[(2 * p) * NPTS + n];
    } else {
        *o = 0.f;
    }
}

// ---------------- launch ----------------
extern "C" void kernel_launch(void* const* d_in, const int* in_sizes, int n_in,
                              void* d_out, int out_size) {
    const float* descriptors = (const float*)d_in[0];
    const int*   mask        = (const int*)d_in[1];
    const float* proj_w      = (const float*)d_in[2];
    const float* proj_b      = (const float*)d_in[3];
    const float* match_w     = (const float*)d_in[4];
    const float* match_b     = (const float*)d_in[5];
    float* out = (float*)d_out;

    proj_gemm<<<dim3(DIM / BN, (BATCH * NPTS) / BM, 1), 256>>>(descriptors, proj_w, proj_b);
    match_kernel<<<(BATCH * NPTS) / 8, 256>>>(descriptors, match_w, match_b);
    sim_gemm<<<dim3(NPTS / BN, NPTS / BM, PAIRS), 256>>>(mask);
    stats_kernel<<<dim3(NCHUNK, PAIRS), 256>>>();
    col_lse_merge<<<(PAIRS * NPTS + 255) / 256, 256>>>();
    final_kernel<<<dim3((NOUT + 255) / 256, NOUT, PAIRS), 256>>>(out);
}

// round 4
// speedup vs baseline: 1.4360x; 1.4360x over previous
#include <cuda_runtime.h>
#include <cuda_bf16.h>
#include <math.h>
#include <float.h>
#include <stdint.h>

// Problem constants
#define BATCH 16
#define PAIRS 8
#define NPTS  2048
#define DIM   256

// GEMM tiling
#define BM 128
#define BN 128
#define BKH 32          // bf16 elements per k-block
#define SW 20           // smem row stride in uint32 (16 data + 4 pad) -> conflict-free

// stats chunking
#define RCH 8
#define NCHUNK (NPTS / RCH)   // 256

// ---------------- device scratch ----------------
__device__ __nv_bfloat16 g_mdescH[(size_t)BATCH * NPTS * DIM];    // 16.8 MB
__device__ float  g_S[(size_t)PAIRS * NPTS * NPTS];               // 134 MB
__device__ float  g_lsP[BATCH * NPTS];
__device__ float  g_lsN[BATCH * NPTS];
__device__ float  g_cpartS[(size_t)NCHUNK * PAIRS * NPTS];        // col sum partials, 16.8 MB
__device__ float2 g_rr[PAIRS * NPTS];                             // (rowActive, lsP0 - rowLse)
__device__ float2 g_cc[PAIRS * NPTS];                             // (colActive, lsP1 - colLse)

// ---------------- helpers ----------------
__device__ __forceinline__ unsigned pack_bf16(float lo, float hi) {
    unsigned r;
    asm("cvt.rn.bf16x2.f32 %0, %1, %2;" : "=r"(r) : "f"(hi), "f"(lo));
    return r;
}

__device__ __forceinline__ void mma_bf16(float c[4], const unsigned a[4], const unsigned b[2]) {
    asm volatile(
        "mma.sync.aligned.m16n8k16.row.col.f32.bf16.bf16.f32 "
        "{%0,%1,%2,%3},{%4,%5,%6,%7},{%8,%9},{%0,%1,%2,%3};"
        : "+f"(c[0]), "+f"(c[1]), "+f"(c[2]), "+f"(c[3])
        : "r"(a[0]), "r"(a[1]), "r"(a[2]), "r"(a[3]), "r"(b[0]), "r"(b[1]));
}

__device__ __forceinline__ float logsigmoidf(float x) {
    return fminf(x, 0.f) - log1pf(expf(-fabsf(x)));
}

__device__ __forceinline__ float warpSum(float v) {
    #pragma unroll
    for (int o = 16; o > 0; o >>= 1) v += __shfl_xor_sync(0xffffffffu, v, o);
    return v;
}

// ---------------- K1: projection GEMM (fp32 in -> bf16 mma -> bf16 out) ----------------
__global__ __launch_bounds__(256) void proj_gemm(const float* __restrict__ A,
                                                 const float* __restrict__ W,
                                                 const float* __restrict__ bias) {
    __shared__ unsigned sA[BM][SW];
    __shared__ unsigned sB[BN][SW];

    const int tid = threadIdx.x;
    const int wid = tid >> 5, lane = tid & 31;
    const int wm = wid >> 2, wn = wid & 3;
    const int g = lane >> 2, t = lane & 3;

    const int rowBase = blockIdx.y * BM;
    const int colBase = blockIdx.x * BN;

    float acc[4][4][4];
    #pragma unroll
    for (int mi = 0; mi < 4; mi++)
        #pragma unroll
        for (int ni = 0; ni < 4; ni++)
            #pragma unroll
            for (int e = 0; e < 4; e++) acc[mi][ni][e] = 0.f;

    for (int kb = 0; kb < DIM; kb += BKH) {
        #pragma unroll
        for (int i = 0; i < 4; i++) {
            int idx = tid + i * 256;
            int r = idx >> 3;
            int c4 = idx & 7;
            float4 va = *(const float4*)(A + (size_t)(rowBase + r) * DIM + kb + c4 * 4);
            sA[r][c4 * 2 + 0] = pack_bf16(va.x, va.y);
            sA[r][c4 * 2 + 1] = pack_bf16(va.z, va.w);
            float4 vb = *(const float4*)(W + (size_t)(colBase + r) * DIM + kb + c4 * 4);
            sB[r][c4 * 2 + 0] = pack_bf16(vb.x, vb.y);
            sB[r][c4 * 2 + 1] = pack_bf16(vb.z, vb.w);
        }
        __syncthreads();

        #pragma unroll
        for (int ks = 0; ks < 2; ks++) {
            const int j0 = ks * 8;
            unsigned a[4][4], b[4][2];
            #pragma unroll
            for (int mi = 0; mi < 4; mi++) {
                int r0 = wm * 64 + mi * 16 + g;
                a[mi][0] = sA[r0][j0 + t];
                a[mi][1] = sA[r0 + 8][j0 + t];
                a[mi][2] = sA[r0][j0 + t + 4];
                a[mi][3] = sA[r0 + 8][j0 + t + 4];
            }
            #pragma unroll
            for (int ni = 0; ni < 4; ni++) {
                int c0 = wn * 32 + ni * 8 + g;
                b[ni][0] = sB[c0][j0 + t];
                b[ni][1] = sB[c0][j0 + t + 4];
            }
            #pragma unroll
            for (int mi = 0; mi < 4; mi++)
                #pragma unroll
                for (int ni = 0; ni < 4; ni++)
                    mma_bf16(acc[mi][ni], a[mi], b[ni]);
        }
        __syncthreads();
    }

    #pragma unroll
    for (int mi = 0; mi < 4; mi++) {
        #pragma unroll
        for (int ni = 0; ni < 4; ni++) {
            #pragma unroll
            for (int eh = 0; eh < 2; eh++) {
                int row = rowBase + wm * 64 + mi * 16 + g + eh * 8;
                int col = colBase + wn * 32 + ni * 8 + 2 * t;
                float v0 = (acc[mi][ni][eh * 2 + 0] + bias[col])     * 0.25f;
                float v1 = (acc[mi][ni][eh * 2 + 1] + bias[col + 1]) * 0.25f;
                *(unsigned*)&g_mdescH[(size_t)row * DIM + col] = pack_bf16(v0, v1);
            }
        }
    }
}

// ---------------- K2: similarity GEMM (bf16, double-buffered) + mask epilogue ----------------
__global__ __launch_bounds__(256) void sim_gemm(const int* __restrict__ mask) {
    __shared__ unsigned sA[2][BM][SW];
    __shared__ unsigned sB[2][BN][SW];

    const int tid = threadIdx.x;
    const int wid = tid >> 5, lane = tid & 31;
    const int wm = wid >> 2, wn = wid & 3;
    const int g = lane >> 2, t = lane & 3;

    const int p = blockIdx.z;
    const int rowBase = blockIdx.y * BM;
    const int colBase = blockIdx.x * BN;

    const __nv_bfloat16* Ap = g_mdescH + (size_t)(2 * p) * NPTS * DIM;
    const __nv_bfloat16* Bp = g_mdescH + (size_t)(2 * p + 1) * NPTS * DIM;

    float acc[4][4][4];
    #pragma unroll
    for (int mi = 0; mi < 4; mi++)
        #pragma unroll
        for (int ni = 0; ni < 4; ni++)
            #pragma unroll
            for (int e = 0; e < 4; e++) acc[mi][ni][e] = 0.f;

    const int r_ld[2]  = { tid >> 2, (tid + 256) >> 2 };
    const int c4_ld[2] = { tid & 3,  (tid + 256) & 3 };

    uint4 pa[2], pb[2];
    #pragma unroll
    for (int i = 0; i < 2; i++) {
        pa[i] = *(const uint4*)(Ap + (size_t)(rowBase + r_ld[i]) * DIM + c4_ld[i] * 8);
        pb[i] = *(const uint4*)(Bp + (size_t)(colBase + r_ld[i]) * DIM + c4_ld[i] * 8);
    }
    #pragma unroll
    for (int i = 0; i < 2; i++) {
        *(uint4*)&sA[0][r_ld[i]][c4_ld[i] * 4] = pa[i];
        *(uint4*)&sB[0][r_ld[i]][c4_ld[i] * 4] = pb[i];
    }
    __syncthreads();

    const int NKB = DIM / BKH;  // 8
    for (int kb = 0; kb < NKB; kb++) {
        const int cur = kb & 1;
        if (kb + 1 < NKB) {
            #pragma unroll
            for (int i = 0; i < 2; i++) {
                pa[i] = *(const uint4*)(Ap + (size_t)(rowBase + r_ld[i]) * DIM + (kb + 1) * BKH + c4_ld[i] * 8);
                pb[i] = *(const uint4*)(Bp + (size_t)(colBase + r_ld[i]) * DIM + (kb + 1) * BKH + c4_ld[i] * 8);
            }
        }

        #pragma unroll
        for (int ks = 0; ks < 2; ks++) {
            const int j0 = ks * 8;
            unsigned a[4][4], b[4][2];
            #pragma unroll
            for (int mi = 0; mi < 4; mi++) {
                int r0 = wm * 64 + mi * 16 + g;
                a[mi][0] = sA[cur][r0][j0 + t];
                a[mi][1] = sA[cur][r0 + 8][j0 + t];
                a[mi][2] = sA[cur][r0][j0 + t + 4];
                a[mi][3] = sA[cur][r0 + 8][j0 + t + 4];
            }
            #pragma unroll
            for (int ni = 0; ni < 4; ni++) {
                int c0 = wn * 32 + ni * 8 + g;
                b[ni][0] = sB[cur][c0][j0 + t];
                b[ni][1] = sB[cur][c0][j0 + t + 4];
            }
            #pragma unroll
            for (int mi = 0; mi < 4; mi++)
                #pragma unroll
                for (int ni = 0; ni < 4; ni++)
                    mma_bf16(acc[mi][ni], a[mi], b[ni]);
        }

        if (kb + 1 < NKB) {
            const int nxt = (kb + 1) & 1;
            #pragma unroll
            for (int i = 0; i < 2; i++) {
                *(uint4*)&sA[nxt][r_ld[i]][c4_ld[i] * 4] = pa[i];
                *(uint4*)&sB[nxt][r_ld[i]][c4_ld[i] * 4] = pb[i];
            }
            __syncthreads();
        }
    }

    // mask epilogue; masked entries are EXACTLY -FLT_MAX
    const int* m0 = mask + (size_t)(2 * p) * NPTS;
    const int* m1 = mask + (size_t)(2 * p + 1) * NPTS;
    float* Sp = g_S + (size_t)p * NPTS * NPTS;

    #pragma unroll
    for (int mi = 0; mi < 4; mi++) {
        int rm[2];
        rm[0] = m0[rowBase + wm * 64 + mi * 16 + g];
        rm[1] = m0[rowBase + wm * 64 + mi * 16 + g + 8];
        #pragma unroll
        for (int ni = 0; ni < 4; ni++) {
            int col = colBase + wn * 32 + ni * 8 + 2 * t;
            int cm0 = m1[col], cm1 = m1[col + 1];
            #pragma unroll
            for (int eh = 0; eh < 2; eh++) {
                int row = rowBase + wm * 64 + mi * 16 + g + eh * 8;
                float2 v;
                v.x = (rm[eh] && cm0) ? acc[mi][ni][eh * 2 + 0] : -FLT_MAX;
                v.y = (rm[eh] && cm1) ? acc[mi][ni][eh * 2 + 1] : -FLT_MAX;
                *(float2*)&Sp[(size_t)row * NPTS + col] = v;
            }
        }
    }
}

// ---------------- K_match: matchability + logsigmoids ----------------
__global__ __launch_bounds__(256) void match_kernel(const float* __restrict__ desc,
                                                    const float* __restrict__ mw,
                                                    const float* __restrict__ mb) {
    int warp = blockIdx.x * 8 + (threadIdx.x >> 5);
    int lane = threadIdx.x & 31;
    const float* dp = desc + (size_t)warp * DIM;
    float acc = 0.f;
    #pragma unroll
    for (int i = 0; i < 8; i++)
        acc = fmaf(dp[lane + 32 * i], mw[lane + 32 * i], acc);
    acc = warpSum(acc);
    if (lane == 0) {
        float m = acc + mb[0];
        g_lsP[warp] = logsigmoidf(m);
        g_lsN[warp] = logsigmoidf(-m);
    }
}

// ---------------- K3: fused row+col exp-sums (no max subtraction) ----------------
// Values are O(1); masked entries are -FLT_MAX -> exp underflows to exactly 0.
// Fully-masked rows handled via the mask input (reference yields -log(2048)).
__global__ __launch_bounds__(256) void stats_kernel(const int* __restrict__ mask) {
    const int p = blockIdx.y;
    const int r0 = blockIdx.x * RCH;
    const int tid = threadIdx.x;
    const int wrp = tid >> 5, lane = tid & 31;

    __shared__ float rp[RCH][256];    // per-row per-thread sums (8 KB)

    float colS[8];
    #pragma unroll
    for (int i = 0; i < 8; i++) colS[i] = 0.f;

    #pragma unroll
    for (int r = 0; r < RCH; r++) {
        const float* row = g_S + ((size_t)p * NPTS + r0 + r) * NPTS;
        float rs = 0.f;
        #pragma unroll
        for (int i = 0; i < 8; i++) {
            float e = __expf(row[tid + 256 * i]);
            colS[i] += e;
            rs += e;
        }
        rp[r][tid] = rs;
    }
    __syncthreads();

    // warp w reduces row w
    {
        int r = wrp;
        float s = rp[r][lane];
        #pragma unroll
        for (int j = 1; j < 8; j++) s += rp[r][lane + 32 * j];
        s = warpSum(s);
        if (lane == 0) {
            int n = r0 + r;
            int active = mask[(size_t)(2 * p) * NPTS + n];
            float lsP0 = g_lsP[(size_t)(2 * p) * NPTS + n];
            float lse = active ? __logf(s) : __logf((float)NPTS);
            g_rr[p * NPTS + n] = make_float2(active ? 1.f : 0.f, lsP0 - lse);
        }
    }

    #pragma unroll
    for (int i = 0; i < 8; i++) {
        int c = tid + 256 * i;
        g_cpartS[((size_t)blockIdx.x * PAIRS + p) * NPTS + c] = colS[i];
    }
}

// ---------------- K4: column merge -> cc ----------------
__global__ __launch_bounds__(256) void col_merge(const int* __restrict__ mask) {
    int idx = blockIdx.x * 256 + threadIdx.x;       // p*NPTS + m
    if (idx >= PAIRS * NPTS) return;
    int p = idx >> 11, m = idx & (NPTS - 1);
    float S = 0.f;
    for (int ch = 0; ch < NCHUNK; ch++)
        S += g_cpartS[(size_t)ch * PAIRS * NPTS + idx];
    int active = mask[(size_t)(2 * p + 1) * NPTS + m];
    float lsP1 = g_lsP[(size_t)(2 * p + 1) * NPTS + m];
    float lse = active ? __logf(S) : __logf((float)NPTS);
    g_cc[idx] = make_float2(active ? 1.f : 0.f, lsP1 - lse);
}

// ---------------- K5: final assembly (aligned 128-bit stores) ----------------
#define NOUT (NPTS + 1)
__global__ __launch_bounds__(256) void final_kernel(float* __restrict__ out) {
    const int n = blockIdx.x;
    const int p = blockIdx.y;
    const int tid = threadIdx.x;

    const float2 rr = g_rr[p * NPTS + n];
    const float2* cc = g_cc + p * NPTS;
    const float* Srow = g_S + ((size_t)p * NPTS + n) * NPTS;
    const float lsN0n = g_lsN[(size_t)(2 * p) * NPTS + n];

    const size_t base = ((size_t)p * NOUT + n) * NOUT;
    const int sh = (int)((4 - (base & 3)) & 3);
    const int K = (NOUT - sh) >> 2;           // # of aligned float4 groups
    const int rem = (NOUT - sh) & 3;

    for (int k = tid; k < K; k += 256) {
        int m0 = sh + 4 * k;
        float4 o;
        float* oc = &o.x;
        #pragma unroll
        for (int c = 0; c < 4; c++) {
            int m = m0 + c;
            if (m < NPTS) {
                float s = __ldg(Srow + m);
                float2 cm = __ldg(cc + m);
                oc[c] = fmaf(rr.x + cm.x, s, rr.y + cm.y);
            } else {
                oc[c] = lsN0n;
            }
        }
        *(float4*)(out + base + m0) = o;
    }

    // head (m < sh) and tail (m >= sh+4K) scalars
    if (tid < sh) {
        int m = tid;
        float s = __ldg(Srow + m);
        float2 cm = __ldg(cc + m);
        out[base + m] = fmaf(rr.x + cm.x, s, rr.y + cm.y);
    } else if (tid >= 4 && tid < 4 + rem) {
        int m = sh + 4 * K + (tid - 4);
        float v;
        if (m < NPTS) {
            float s = __ldg(Srow + m);
            float2 cm = __ldg(cc + m);
            v = fmaf(rr.x + cm.x, s, rr.y + cm.y);
        } else {
            v = lsN0n;
        }
        out[base + m] = v;
    }
}

// border row n==NPTS: out[p][NPTS][m] = logsigmoid(-m1)[m], corner = 0
__global__ __launch_bounds__(256) void border_kernel(float* __restrict__ out) {
    int m = blockIdx.x * 256 + threadIdx.x;
    int p = blockIdx.y;
    if (m >= NOUT) return;
    float v = (m < NPTS) ? g_lsN[(size_t)(2 * p + 1) * NPTS + m] : 0.f;
    out[((size_t)p * NOUT + NPTS) * NOUT + m] = v;
}

// ---------------- launch ----------------
extern "C" void kernel_launch(void* const* d_in, const int* in_sizes, int n_in,
                              void* d_out, int out_size) {
    const float* descriptors = (const float*)d_in[0];
    const int*   mask        = (const int*)d_in[1];
    const float* proj_w      = (const float*)d_in[2];
    const float* proj_b      = (const float*)d_in[3];
    const float* match_w     = (const float*)d_in[4];
    const float* match_b     = (const float*)d_in[5];
    float* out = (float*)d_out;

    proj_gemm<<<dim3(DIM / BN, (BATCH * NPTS) / BM, 1), 256>>>(descriptors, proj_w, proj_b);
    match_kernel<<<(BATCH * NPTS) / 8, 256>>>(descriptors, match_w, match_b);
    sim_gemm<<<dim3(NPTS / BN, NPTS / BM, PAIRS), 256>>>(mask);
    stats_kernel<<<dim3(NCHUNK, PAIRS), 256>>>(mask);
    col_merge<<<(PAIRS * NPTS + 255) / 256, 256>>>(mask);
    final_kernel<<<dim3(NPTS, PAIRS), 256>>>(out);
    border_kernel<<<dim3((NOUT + 255) / 256, PAIRS), 256>>>(out);
}

// round 5
// speedup vs baseline: 1.6037x; 1.1168x over previous
#include <cuda_runtime.h>
#include <cuda_bf16.h>
#include <math.h>
#include <float.h>
#include <stdint.h>

// Problem constants
#define BATCH 16
#define PAIRS 8
#define NPTS  2048
#define DIM   256

// GEMM tiling
#define BM 128
#define BN 128
#define BKH 32          // bf16 elements per k-block
#define SW 20           // smem row stride in uint32 (16 data + 4 pad) -> conflict-free

// ---------------- device scratch ----------------
__device__ __nv_bfloat16 g_mdescH[(size_t)BATCH * NPTS * DIM];    // 16.8 MB
__device__ __nv_bfloat16 g_Sh[(size_t)PAIRS * NPTS * NPTS];       // 67 MB (bf16 S)
__device__ float  g_lsP[BATCH * NPTS];
__device__ float  g_lsN[BATCH * NPTS];
__device__ float  g_rowS[PAIRS * NPTS];                           // exp-sum accumulators
__device__ float  g_colS[PAIRS * NPTS];
__device__ float2 g_rr[PAIRS * NPTS];                             // (rowActive, lsP0 - rowLse)
__device__ float2 g_cc[PAIRS * NPTS];                             // (colActive, lsP1 - colLse)

// ---------------- helpers ----------------
__device__ __forceinline__ unsigned pack_bf16(float lo, float hi) {
    unsigned r;
    asm("cvt.rn.bf16x2.f32 %0, %1, %2;" : "=r"(r) : "f"(hi), "f"(lo));
    return r;
}

__device__ __forceinline__ void mma_bf16(float c[4], const unsigned a[4], const unsigned b[2]) {
    asm volatile(
        "mma.sync.aligned.m16n8k16.row.col.f32.bf16.bf16.f32 "
        "{%0,%1,%2,%3},{%4,%5,%6,%7},{%8,%9},{%0,%1,%2,%3};"
        : "+f"(c[0]), "+f"(c[1]), "+f"(c[2]), "+f"(c[3])
        : "r"(a[0]), "r"(a[1]), "r"(a[2]), "r"(a[3]), "r"(b[0]), "r"(b[1]));
}

__device__ __forceinline__ float logsigmoidf(float x) {
    return fminf(x, 0.f) - log1pf(expf(-fabsf(x)));
}

__device__ __forceinline__ float warpSum(float v) {
    #pragma unroll
    for (int o = 16; o > 0; o >>= 1) v += __shfl_xor_sync(0xffffffffu, v, o);
    return v;
}

// ---------------- K0: zero accumulators ----------------
__global__ __launch_bounds__(256) void init_kernel() {
    int i = blockIdx.x * 256 + threadIdx.x;
    if (i < PAIRS * NPTS) { g_rowS[i] = 0.f; g_colS[i] = 0.f; }
}

// ---------------- K1: projection GEMM (fp32 in -> bf16 mma -> bf16 out) ----------------
__global__ __launch_bounds__(256) void proj_gemm(const float* __restrict__ A,
                                                 const float* __restrict__ W,
                                                 const float* __restrict__ bias) {
    __shared__ unsigned sA[BM][SW];
    __shared__ unsigned sB[BN][SW];

    const int tid = threadIdx.x;
    const int wid = tid >> 5, lane = tid & 31;
    const int wm = wid >> 2, wn = wid & 3;
    const int g = lane >> 2, t = lane & 3;

    const int rowBase = blockIdx.y * BM;
    const int colBase = blockIdx.x * BN;

    float acc[4][4][4];
    #pragma unroll
    for (int mi = 0; mi < 4; mi++)
        #pragma unroll
        for (int ni = 0; ni < 4; ni++)
            #pragma unroll
            for (int e = 0; e < 4; e++) acc[mi][ni][e] = 0.f;

    for (int kb = 0; kb < DIM; kb += BKH) {
        #pragma unroll
        for (int i = 0; i < 4; i++) {
            int idx = tid + i * 256;
            int r = idx >> 3;
            int c4 = idx & 7;
            float4 va = *(const float4*)(A + (size_t)(rowBase + r) * DIM + kb + c4 * 4);
            sA[r][c4 * 2 + 0] = pack_bf16(va.x, va.y);
            sA[r][c4 * 2 + 1] = pack_bf16(va.z, va.w);
            float4 vb = *(const float4*)(W + (size_t)(colBase + r) * DIM + kb + c4 * 4);
            sB[r][c4 * 2 + 0] = pack_bf16(vb.x, vb.y);
            sB[r][c4 * 2 + 1] = pack_bf16(vb.z, vb.w);
        }
        __syncthreads();

        #pragma unroll
        for (int ks = 0; ks < 2; ks++) {
            const int j0 = ks * 8;
            unsigned a[4][4], b[4][2];
            #pragma unroll
            for (int mi = 0; mi < 4; mi++) {
                int r0 = wm * 64 + mi * 16 + g;
                a[mi][0] = sA[r0][j0 + t];
                a[mi][1] = sA[r0 + 8][j0 + t];
                a[mi][2] = sA[r0][j0 + t + 4];
                a[mi][3] = sA[r0 + 8][j0 + t + 4];
            }
            #pragma unroll
            for (int ni = 0; ni < 4; ni++) {
                int c0 = wn * 32 + ni * 8 + g;
                b[ni][0] = sB[c0][j0 + t];
                b[ni][1] = sB[c0][j0 + t + 4];
            }
            #pragma unroll
            for (int mi = 0; mi < 4; mi++)
                #pragma unroll
                for (int ni = 0; ni < 4; ni++)
                    mma_bf16(acc[mi][ni], a[mi], b[ni]);
        }
        __syncthreads();
    }

    #pragma unroll
    for (int mi = 0; mi < 4; mi++) {
        #pragma unroll
        for (int ni = 0; ni < 4; ni++) {
            #pragma unroll
            for (int eh = 0; eh < 2; eh++) {
                int row = rowBase + wm * 64 + mi * 16 + g + eh * 8;
                int col = colBase + wn * 32 + ni * 8 + 2 * t;
                float v0 = (acc[mi][ni][eh * 2 + 0] + bias[col])     * 0.25f;
                float v1 = (acc[mi][ni][eh * 2 + 1] + bias[col + 1]) * 0.25f;
                *(unsigned*)&g_mdescH[(size_t)row * DIM + col] = pack_bf16(v0, v1);
            }
        }
    }
}

// ---------------- K2: similarity GEMM + fused mask/exp-sum epilogue ----------------
__global__ __launch_bounds__(256) void sim_gemm(const int* __restrict__ mask) {
    __shared__ unsigned sA[2][BM][SW];
    __shared__ unsigned sB[2][BN][SW];
    __shared__ float sRow[BM];
    __shared__ float sCol[BN];

    const int tid = threadIdx.x;
    const int wid = tid >> 5, lane = tid & 31;
    const int wm = wid >> 2, wn = wid & 3;
    const int g = lane >> 2, t = lane & 3;

    const int p = blockIdx.z;
    const int rowBase = blockIdx.y * BM;
    const int colBase = blockIdx.x * BN;

    const __nv_bfloat16* Ap = g_mdescH + (size_t)(2 * p) * NPTS * DIM;
    const __nv_bfloat16* Bp = g_mdescH + (size_t)(2 * p + 1) * NPTS * DIM;

    float acc[4][4][4];
    #pragma unroll
    for (int mi = 0; mi < 4; mi++)
        #pragma unroll
        for (int ni = 0; ni < 4; ni++)
            #pragma unroll
            for (int e = 0; e < 4; e++) acc[mi][ni][e] = 0.f;

    const int r_ld[2]  = { tid >> 2, (tid + 256) >> 2 };
    const int c4_ld[2] = { tid & 3,  (tid + 256) & 3 };

    if (tid < BM) sRow[tid] = 0.f;
    else sCol[tid - BM] = 0.f;

    uint4 pa[2], pb[2];
    #pragma unroll
    for (int i = 0; i < 2; i++) {
        pa[i] = *(const uint4*)(Ap + (size_t)(rowBase + r_ld[i]) * DIM + c4_ld[i] * 8);
        pb[i] = *(const uint4*)(Bp + (size_t)(colBase + r_ld[i]) * DIM + c4_ld[i] * 8);
    }
    #pragma unroll
    for (int i = 0; i < 2; i++) {
        *(uint4*)&sA[0][r_ld[i]][c4_ld[i] * 4] = pa[i];
        *(uint4*)&sB[0][r_ld[i]][c4_ld[i] * 4] = pb[i];
    }
    __syncthreads();

    const int NKB = DIM / BKH;  // 8
    for (int kb = 0; kb < NKB; kb++) {
        const int cur = kb & 1;
        if (kb + 1 < NKB) {
            #pragma unroll
            for (int i = 0; i < 2; i++) {
                pa[i] = *(const uint4*)(Ap + (size_t)(rowBase + r_ld[i]) * DIM + (kb + 1) * BKH + c4_ld[i] * 8);
                pb[i] = *(const uint4*)(Bp + (size_t)(colBase + r_ld[i]) * DIM + (kb + 1) * BKH + c4_ld[i] * 8);
            }
        }

        #pragma unroll
        for (int ks = 0; ks < 2; ks++) {
            const int j0 = ks * 8;
            unsigned a[4][4], b[4][2];
            #pragma unroll
            for (int mi = 0; mi < 4; mi++) {
                int r0 = wm * 64 + mi * 16 + g;
                a[mi][0] = sA[cur][r0][j0 + t];
                a[mi][1] = sA[cur][r0 + 8][j0 + t];
                a[mi][2] = sA[cur][r0][j0 + t + 4];
                a[mi][3] = sA[cur][r0 + 8][j0 + t + 4];
            }
            #pragma unroll
            for (int ni = 0; ni < 4; ni++) {
                int c0 = wn * 32 + ni * 8 + g;
                b[ni][0] = sB[cur][c0][j0 + t];
                b[ni][1] = sB[cur][c0][j0 + t + 4];
            }
            #pragma unroll
            for (int mi = 0; mi < 4; mi++)
                #pragma unroll
                for (int ni = 0; ni < 4; ni++)
                    mma_bf16(acc[mi][ni], a[mi], b[ni]);
        }

        if (kb + 1 < NKB) {
            const int nxt = (kb + 1) & 1;
            #pragma unroll
            for (int i = 0; i < 2; i++) {
                *(uint4*)&sA[nxt][r_ld[i]][c4_ld[i] * 4] = pa[i];
                *(uint4*)&sB[nxt][r_ld[i]][c4_ld[i] * 4] = pb[i];
            }
            __syncthreads();
        }
    }

    // Epilogue: mask -> bf16 store + exp-sum accumulation.
    // Masked entries get -FLT_MAX (bf16-rounded on store; consumers snap back).
    const int* m0 = mask + (size_t)(2 * p) * NPTS;
    const int* m1 = mask + (size_t)(2 * p + 1) * NPTS;
    __nv_bfloat16* Sp = g_Sh + (size_t)p * NPTS * NPTS;

    float rowP[4][2];   // [mi][eh]
    float colP[4][2];   // [ni][c]
    #pragma unroll
    for (int i = 0; i < 4; i++) { rowP[i][0] = rowP[i][1] = 0.f; colP[i][0] = colP[i][1] = 0.f; }

    #pragma unroll
    for (int mi = 0; mi < 4; mi++) {
        int rm[2];
        rm[0] = m0[rowBase + wm * 64 + mi * 16 + g];
        rm[1] = m0[rowBase + wm * 64 + mi * 16 + g + 8];
        #pragma unroll
        for (int ni = 0; ni < 4; ni++) {
            int col = colBase + wn * 32 + ni * 8 + 2 * t;
            int cm0 = m1[col], cm1 = m1[col + 1];
            #pragma unroll
            for (int eh = 0; eh < 2; eh++) {
                int row = rowBase + wm * 64 + mi * 16 + g + eh * 8;
                float vx = (rm[eh] && cm0) ? acc[mi][ni][eh * 2 + 0] : -FLT_MAX;
                float vy = (rm[eh] && cm1) ? acc[mi][ni][eh * 2 + 1] : -FLT_MAX;
                *(unsigned*)&Sp[(size_t)row * NPTS + col] = pack_bf16(vx, vy);
                float e0 = __expf(vx);   // exp(-FLT_MAX) == 0
                float e1 = __expf(vy);
                rowP[mi][eh] += e0 + e1;
                colP[ni][0] += e0;
                colP[ni][1] += e1;
            }
        }
    }

    __syncthreads();   // sRow/sCol zeroed earlier; all warps past mainloop

    // row partials: reduce over t (lanes xor 1,2), then smem-accumulate
    #pragma unroll
    for (int mi = 0; mi < 4; mi++)
        #pragma unroll
        for (int eh = 0; eh < 2; eh++) {
            float r = rowP[mi][eh];
            r += __shfl_xor_sync(0xffffffffu, r, 1);
            r += __shfl_xor_sync(0xffffffffu, r, 2);
            if (t == 0) atomicAdd(&sRow[wm * 64 + mi * 16 + g + eh * 8], r);
        }
    // col partials: reduce over g (lanes xor 4,8,16)
    #pragma unroll
    for (int ni = 0; ni < 4; ni++)
        #pragma unroll
        for (int c = 0; c < 2; c++) {
            float v = colP[ni][c];
            v += __shfl_xor_sync(0xffffffffu, v, 4);
            v += __shfl_xor_sync(0xffffffffu, v, 8);
            v += __shfl_xor_sync(0xffffffffu, v, 16);
            if (g == 0) atomicAdd(&sCol[wn * 32 + ni * 8 + 2 * t + c], v);
        }
    __syncthreads();

    if (tid < BM) atomicAdd(&g_rowS[p * NPTS + rowBase + tid], sRow[tid]);
    else          atomicAdd(&g_colS[p * NPTS + colBase + (tid - BM)], sCol[tid - BM]);
}

// ---------------- K_match: matchability + logsigmoids ----------------
__global__ __launch_bounds__(256) void match_kernel(const float* __restrict__ desc,
                                                    const float* __restrict__ mw,
                                                    const float* __restrict__ mb) {
    int warp = blockIdx.x * 8 + (threadIdx.x >> 5);
    int lane = threadIdx.x & 31;
    const float* dp = desc + (size_t)warp * DIM;
    float acc = 0.f;
    #pragma unroll
    for (int i = 0; i < 8; i++)
        acc = fmaf(dp[lane + 32 * i], mw[lane + 32 * i], acc);
    acc = warpSum(acc);
    if (lane == 0) {
        float m = acc + mb[0];
        g_lsP[warp] = logsigmoidf(m);
        g_lsN[warp] = logsigmoidf(-m);
    }
}

// ---------------- K3: finish rr/cc from accumulated sums ----------------
__global__ __launch_bounds__(256) void finish_kernel(const int* __restrict__ mask) {
    int idx = blockIdx.x * 256 + threadIdx.x;       // p*NPTS + i
    if (idx >= PAIRS * NPTS) return;
    int p = idx >> 11, i = idx & (NPTS - 1);

    int a0 = mask[(size_t)(2 * p) * NPTS + i];
    float l0 = a0 ? __logf(g_rowS[idx]) : __logf((float)NPTS);
    g_rr[idx] = make_float2(a0 ? 1.f : 0.f, g_lsP[(size_t)(2 * p) * NPTS + i] - l0);

    int a1 = mask[(size_t)(2 * p + 1) * NPTS + i];
    float l1 = a1 ? __logf(g_colS[idx]) : __logf((float)NPTS);
    g_cc[idx] = make_float2(a1 ? 1.f : 0.f, g_lsP[(size_t)(2 * p + 1) * NPTS + i] - l1);
}

// ---------------- K5: final assembly (aligned 128-bit stores, bf16 S read) ----------------
#define NOUT (NPTS + 1)
__global__ __launch_bounds__(256) void final_kernel(float* __restrict__ out) {
    const int n = blockIdx.x;
    const int p = blockIdx.y;
    const int tid = threadIdx.x;

    const float2 rr = g_rr[p * NPTS + n];
    const float2* cc = g_cc + p * NPTS;
    const __nv_bfloat16* Srow = g_Sh + ((size_t)p * NPTS + n) * NPTS;
    const float lsN0n = g_lsN[(size_t)(2 * p) * NPTS + n];

    const size_t base = ((size_t)p * NOUT + n) * NOUT;
    const int sh = (int)((4 - (base & 3)) & 3);
    const int K = (NOUT - sh) >> 2;
    const int rem = (NOUT - sh) & 3;

    for (int k = tid; k < K; k += 256) {
        int m0 = sh + 4 * k;
        float4 o;
        float* oc = &o.x;
        #pragma unroll
        for (int c = 0; c < 4; c++) {
            int m = m0 + c;
            if (m < NPTS) {
                float s = __bfloat162float(__ldg(Srow + m));
                if (s < -1e38f) s = -FLT_MAX;
                float2 cm = __ldg(cc + m);
                oc[c] = fmaf(rr.x + cm.x, s, rr.y + cm.y);
            } else {
                oc[c] = lsN0n;
            }
        }
        *(float4*)(out + base + m0) = o;
    }

    if (tid < sh) {
        int m = tid;
        float s = __bfloat162float(__ldg(Srow + m));
        if (s < -1e38f) s = -FLT_MAX;
        float2 cm = __ldg(cc + m);
        out[base + m] = fmaf(rr.x + cm.x, s, rr.y + cm.y);
    } else if (tid >= 4 && tid < 4 + rem) {
        int m = sh + 4 * K + (tid - 4);
        float v;
        if (m < NPTS) {
            float s = __bfloat162float(__ldg(Srow + m));
            if (s < -1e38f) s = -FLT_MAX;
            float2 cm = __ldg(cc + m);
            v = fmaf(rr.x + cm.x, s, rr.y + cm.y);
        } else {
            v = lsN0n;
        }
        out[base + m] = v;
    }
}

// border row n==NPTS
__global__ __launch_bounds__(256) void border_kernel(float* __restrict__ out) {
    int m = blockIdx.x * 256 + threadIdx.x;
    int p = blockIdx.y;
    if (m >= NOUT) return;
    float v = (m < NPTS) ? g_lsN[(size_t)(2 * p + 1) * NPTS + m] : 0.f;
    out[((size_t)p * NOUT + NPTS) * NOUT + m] = v;
}

// ---------------- launch ----------------
extern "C" void kernel_launch(void* const* d_in, const int* in_sizes, int n_in,
                              void* d_out, int out_size) {
    const float* descriptors = (const float*)d_in[0];
    const int*   mask        = (const int*)d_in[1];
    const float* proj_w      = (const float*)d_in[2];
    const float* proj_b      = (const float*)d_in[3];
    const float* match_w     = (const float*)d_in[4];
    const float* match_b     = (const float*)d_in[5];
    float* out = (float*)d_out;

    init_kernel<<<(PAIRS * NPTS + 255) / 256, 256>>>();
    proj_gemm<<<dim3(DIM / BN, (BATCH * NPTS) / BM, 1), 256>>>(descriptors, proj_w, proj_b);
    match_kernel<<<(BATCH * NPTS) / 8, 256>>>(descriptors, match_w, match_b);
    sim_gemm<<<dim3(NPTS / BN, NPTS / BM, PAIRS), 256>>>(mask);
    finish_kernel<<<(PAIRS * NPTS + 255) / 256, 256>>>(mask);
    final_kernel<<<dim3(NPTS, PAIRS), 256>>>(out);
    border_kernel<<<dim3((NOUT + 255) / 256, PAIRS), 256>>>(out);
}